// round 4
// baseline (speedup 1.0000x reference)
#include <cuda_runtime.h>
#include <cmath>
#include <complex>
#include <algorithm>

// ----------------------------------------------------------------------------
// Problem constants
// ----------------------------------------------------------------------------
#define NNODES   50000
#define C_DIM    128
#define M_DIM    9
#define B_NODES  16
#define THREADS  256

#define SX_F     (B_NODES * M_DIM * 256)     // 36864 floats: dup x tile, later dup t
#define SW_ROWA  65                          // float4 per k-row (64 + 1 pad)
#define SW_ROWC  65                          // float2 per k-row (64 + 1 pad)
#define SW_F     16640                       // max(64*65*4, 128*65*2) floats
#define SMEM_BYTES ((SX_F + SW_F) * 4)       // 214016 B

typedef unsigned long long ull;

// Wigner-3j tables (alpha folded in), kernel arg.
struct W3J {
    float w220[25];
    float w121[45];
    float w112[45];
};

// ----------------------------------------------------------------------------
// Host-side Wigner 3j (literal translation of the reference, double precision)
// ----------------------------------------------------------------------------
namespace hw3j {
typedef std::complex<double> cd;

static inline double fact(int n) { double r = 1.0; for (int i = 2; i <= n; ++i) r *= (double)i; return r; }

static double su2_cg(int j1, int m1, int j2, int m2, int j3, int m3) {
    if (m1 + m2 != m3) return 0.0;
    int vmin = std::max(std::max(-j1 + j2 + m3, -j1 + m1), 0);
    int vmax = std::min(std::min(j2 + j3 + m1, j3 - j1 + j2), j3 + m3);
    double pref = std::sqrt((2.0 * j3 + 1.0)
        * fact(j3 + j1 - j2) * fact(j3 - j1 + j2) * fact(j1 + j2 - j3) / fact(j1 + j2 + j3 + 1)
        * fact(j3 + m3) * fact(j3 - m3)
        / (fact(j1 - m1) * fact(j1 + m1) * fact(j2 - m2) * fact(j2 + m2)));
    double s = 0.0;
    for (int v = vmin; v <= vmax; ++v) {
        double sgn = ((v + j2 + m2) & 1) ? -1.0 : 1.0;
        s += sgn / fact(v) * fact(j2 + j3 + m1 - v) * fact(j1 - m1 + v)
             / (fact(j3 - j1 + j2 - v) * fact(j3 + m3 - v) * fact(v + j1 - j2 - m3));
    }
    return pref * s;
}

static void qmat(int l, cd q[5][5]) {
    for (int a = 0; a < 5; ++a) for (int b = 0; b < 5; ++b) q[a][b] = cd(0, 0);
    const double is2 = 1.0 / std::sqrt(2.0);
    for (int m = -l; m < 0; ++m) {
        q[l + m][l - m] = cd(is2, 0.0);
        q[l + m][l + m] = cd(0.0, -is2);
    }
    q[l][l] = cd(1.0, 0.0);
    for (int m = 1; m <= l; ++m) {
        double sg = (m & 1) ? -1.0 : 1.0;
        q[l + m][l + m] = cd(sg * is2, 0.0);
        q[l + m][l - m] = cd(0.0, sg * is2);
    }
    cd ph;
    switch (l & 3) {
        case 0: ph = cd( 1,  0); break;
        case 1: ph = cd( 0, -1); break;
        case 2: ph = cd(-1,  0); break;
        default: ph = cd(0,  1); break;
    }
    for (int a = 0; a < 2 * l + 1; ++a) for (int b = 0; b < 2 * l + 1; ++b) q[a][b] *= ph;
}

static void wig3j(int l1, int l2, int l3, float* out) {
    const int d1 = 2 * l1 + 1, d2 = 2 * l2 + 1, d3 = 2 * l3 + 1;
    cd Q1[5][5], Q2[5][5], Q3[5][5];
    qmat(l1, Q1); qmat(l2, Q2); qmat(l3, Q3);
    static cd Csu2[5][5][5];
    for (int i = 0; i < d1; ++i)
        for (int k = 0; k < d2; ++k)
            for (int n = 0; n < d3; ++n)
                Csu2[i][k][n] = cd(su2_cg(l1, i - l1, l2, k - l2, l3, n - l3), 0.0);
    static double Cr[5][5][5];
    double nrm = 0.0;
    for (int j = 0; j < d1; ++j)
        for (int ll = 0; ll < d2; ++ll)
            for (int m = 0; m < d3; ++m) {
                cd acc(0, 0);
                for (int i = 0; i < d1; ++i)
                    for (int k = 0; k < d2; ++k)
                        for (int n = 0; n < d3; ++n)
                            acc += Q1[i][j] * Q2[k][ll] * std::conj(Q3[n][m]) * Csu2[i][k][n];
                Cr[j][ll][m] = acc.real();
                nrm += acc.real() * acc.real();
            }
    nrm = std::sqrt(nrm);
    int idx = 0;
    for (int j = 0; j < d1; ++j)
        for (int ll = 0; ll < d2; ++ll)
            for (int m = 0; m < d3; ++m)
                out[idx++] = (float)(Cr[j][ll][m] / nrm);
}

static void build(W3J& P) {
    float c220[25], c121[45], c112[45];
    wig3j(2, 2, 0, c220);
    wig3j(1, 2, 1, c121);
    wig3j(1, 1, 2, c112);
    const float a121 = std::sqrt(3.0f), a112 = std::sqrt(5.0f);
    for (int i = 0; i < 25; ++i) P.w220[i] = c220[i];
    for (int i = 0; i < 45; ++i) P.w121[i] = a121 * c121[i];
    for (int i = 0; i < 45; ++i) P.w112[i] = a112 * c112[i];
}
} // namespace hw3j

// ----------------------------------------------------------------------------
// Packed fp32 helpers
// ----------------------------------------------------------------------------
__device__ __forceinline__ void fma2(ull& acc, ull a, ull b) {
    asm("fma.rn.f32x2 %0, %1, %2, %0;" : "+l"(acc) : "l"(a), "l"(b));
}
__device__ __forceinline__ float f2lo(ull v) { return __uint_as_float((unsigned int)v); }
__device__ __forceinline__ float f2hi(ull v) { return __uint_as_float((unsigned int)(v >> 32)); }

// ----------------------------------------------------------------------------
// Fused kernel. 256 threads:
//   d5 = tid & 63   -> owns channel pair {d5, d5+64} (packed in f32x2 lanes)
//   ng = tid >> 6   -> owns nodes {4ng .. 4ng+3} of the 16-node tile
// Stage A: accL/accR[4 nodes][9 m] f32x2 {chan lo, chan hi}; x dup-broadcast
//          feeds both channels and both matrices.
// Stage B: TP per channel in registers -> t (dup) into sx region.
// Stage C: final linear, same {lo,hi} packing.
// ----------------------------------------------------------------------------
__global__ __launch_bounds__(THREADS, 1)
void b2i_fused_kernel(const float* __restrict__ x,
                      const float* __restrict__ Wl, const float* __restrict__ bl,
                      const float* __restrict__ Wr, const float* __restrict__ br,
                      const float* __restrict__ Wf, const float* __restrict__ bf,
                      float* __restrict__ out, const W3J P)
{
    extern __shared__ float smem[];
    float* sx = smem;            // dup x tile [16][9][128*2]; later dup t
    float* sw = smem + SX_F;     // weight staging

    const int tid = threadIdx.x;
    const int d5  = tid & 63;
    const int ng  = tid >> 6;                 // 0..3
    const size_t node0 = (size_t)blockIdx.x * B_NODES;

    // ---- load x tile into duplicated layout: row=(node*9+m), float[2c]=float[2c+1]=x[c] ----
    {
        const float2* gx = reinterpret_cast<const float2*>(x + node0 * M_DIM * C_DIM);
        #pragma unroll
        for (int i = 0; i < (B_NODES * M_DIM * C_DIM / 2) / THREADS; ++i) {
            const int q = tid + i * THREADS;      // float2 index
            const float2 g = gx[q];
            const int row = q >> 6;
            const int cp  = q & 63;
            *reinterpret_cast<float4*>(sx + row * 256 + cp * 4) =
                make_float4(g.x, g.x, g.y, g.y);
        }
    }

    const float bl_lo = bl[d5],      bl_hi = bl[d5 + 64];
    const float br_lo = br[d5],      br_hi = br[d5 + 64];
    const float bf_lo = bf[d5],      bf_hi = bf[d5 + 64];

    // =========================================================================
    // Stage A: left/right linears. acc = f32x2 {chan d5, chan d5+64}.
    // =========================================================================
    ull accL[4][M_DIM], accR[4][M_DIM];
    #pragma unroll
    for (int n = 0; n < 4; ++n)
        #pragma unroll
        for (int m = 0; m < M_DIM; ++m) { accL[n][m] = 0ULL; accR[n][m] = 0ULL; }

    for (int l = 0; l < 3; ++l) {
        const int base = l * l, msz = 2 * l + 1;
        for (int half = 0; half < 2; ++half) {
            __syncthreads();   // x ready (first) / prev chunk compute done
            // ---- stage: sw4[k][dd] = {Wl[dd][K], Wl[dd+64][K], Wr[dd][K], Wr[dd+64][K]}, K=64*half+k ----
            {
                float4* sw4 = reinterpret_cast<float4*>(sw);
                #pragma unroll
                for (int i = 0; i < 16; ++i) {
                    const int idx = tid + i * THREADS;   // 0..4095
                    const int k  = idx & 63;
                    const int dd = idx >> 6;             // 0..63
                    const size_t K = (size_t)half * 64 + k;
                    const size_t rlo = (size_t)(l * 128 + dd) * 128 + K;
                    const size_t rhi = (size_t)(l * 128 + dd + 64) * 128 + K;
                    sw4[k * SW_ROWA + dd] =
                        make_float4(__ldg(Wl + rlo), __ldg(Wl + rhi),
                                    __ldg(Wr + rlo), __ldg(Wr + rhi));
                }
            }
            __syncthreads();
            // ---- compute ----
            const ulonglong2* sw4u = reinterpret_cast<const ulonglong2*>(sw);
            #pragma unroll 4
            for (int q = 0; q < 32; ++q) {               // k-pair within chunk
                const ulonglong2 w0 = sw4u[(2 * q)     * SW_ROWA + d5]; // k=2q:   {Wl lo,hi},{Wr lo,hi}
                const ulonglong2 w1 = sw4u[(2 * q + 1) * SW_ROWA + d5]; // k=2q+1
                #pragma unroll
                for (int n = 0; n < 4; ++n) {
                    const float* xb = sx + ((ng * 4 + n) * M_DIM + base) * 256
                                         + (half * 64 + 2 * q) * 2;
                    #pragma unroll
                    for (int mm = 0; mm < msz; ++mm) {
                        const ulonglong2 xv =
                            *reinterpret_cast<const ulonglong2*>(xb + mm * 256); // broadcast
                        fma2(accL[n][base + mm], xv.x, w0.x);
                        fma2(accR[n][base + mm], xv.x, w0.y);
                        fma2(accL[n][base + mm], xv.y, w1.x);
                        fma2(accR[n][base + mm], xv.y, w1.y);
                    }
                }
            }
        }
    }

    // =========================================================================
    // Stage B: bias + CG tensor product per channel -> dup t into sx region
    // =========================================================================
    __syncthreads();   // all stage-A reads of sx complete before overwrite
    float* st = sx;
    #pragma unroll
    for (int n = 0; n < 4; ++n) {
        const int node = ng * 4 + n;
        #pragma unroll
        for (int h = 0; h < 2; ++h) {          // h=0: chan d5, h=1: chan d5+64
            float L[M_DIM], R[M_DIM];
            #pragma unroll
            for (int m = 0; m < M_DIM; ++m) {
                L[m] = h ? f2hi(accL[n][m]) : f2lo(accL[n][m]);
                R[m] = h ? f2hi(accR[n][m]) : f2lo(accR[n][m]);
            }
            L[0] += h ? bl_hi : bl_lo;
            R[0] += h ? br_hi : br_lo;

            float t[M_DIM];
            {   // (2,2,0)
                float v = 0.f;
                #pragma unroll
                for (int i = 0; i < 5; ++i)
                    #pragma unroll
                    for (int j = 0; j < 5; ++j)
                        v = fmaf(P.w220[i * 5 + j], L[4 + i] * R[4 + j], v);
                t[0] = v;
            }
            #pragma unroll
            for (int k = 0; k < 3; ++k) {   // (1,2,1)
                float v = 0.f;
                #pragma unroll
                for (int i = 0; i < 3; ++i)
                    #pragma unroll
                    for (int j = 0; j < 5; ++j)
                        v = fmaf(P.w121[(i * 5 + j) * 3 + k], L[1 + i] * R[4 + j], v);
                t[1 + k] = v;
            }
            #pragma unroll
            for (int k = 0; k < 5; ++k) {   // (1,1,2)
                float v = 0.f;
                #pragma unroll
                for (int i = 0; i < 3; ++i)
                    #pragma unroll
                    for (int j = 0; j < 3; ++j)
                        v = fmaf(P.w112[(i * 3 + j) * 5 + k], L[1 + i] * R[1 + j], v);
                t[4 + k] = v;
            }
            const int c = d5 + h * 64;
            #pragma unroll
            for (int m = 0; m < M_DIM; ++m)
                *reinterpret_cast<float2*>(st + (node * M_DIM + m) * 256 + c * 2)
                    = make_float2(t[m], t[m]);
        }
    }

    // =========================================================================
    // Stage C: final linear, packed {chan d5, chan d5+64}
    // =========================================================================
    ull acc2[4][M_DIM];
    #pragma unroll
    for (int n = 0; n < 4; ++n)
        #pragma unroll
        for (int m = 0; m < M_DIM; ++m) acc2[n][m] = 0ULL;

    for (int l = 0; l < 3; ++l) {
        const int base = l * l, msz = 2 * l + 1;
        __syncthreads();   // t writes done (first) / prev-l compute done
        // ---- stage: sw2[k][dd] = {Wf[dd][k], Wf[dd+64][k]} ----
        {
            float2* sw2 = reinterpret_cast<float2*>(sw);
            #pragma unroll
            for (int i = 0; i < 32; ++i) {
                const int idx = tid + i * THREADS;    // 0..8191
                const int k  = idx & 127;
                const int dd = idx >> 7;              // 0..63
                sw2[k * SW_ROWC + dd] =
                    make_float2(__ldg(Wf + (size_t)(l * 128 + dd) * 128 + k),
                                __ldg(Wf + (size_t)(l * 128 + dd + 64) * 128 + k));
            }
        }
        __syncthreads();
        // ---- compute ----
        const ull* sw2u = reinterpret_cast<const ull*>(sw);
        #pragma unroll 4
        for (int q = 0; q < 64; ++q) {               // k-pair
            const ull w0 = sw2u[(2 * q)     * SW_ROWC + d5];
            const ull w1 = sw2u[(2 * q + 1) * SW_ROWC + d5];
            #pragma unroll
            for (int n = 0; n < 4; ++n) {
                const float* tb = st + ((ng * 4 + n) * M_DIM + base) * 256 + 4 * q;
                #pragma unroll
                for (int mm = 0; mm < msz; ++mm) {
                    const ulonglong2 tv =
                        *reinterpret_cast<const ulonglong2*>(tb + mm * 256); // broadcast
                    fma2(acc2[n][base + mm], tv.x, w0);
                    fma2(acc2[n][base + mm], tv.y, w1);
                }
            }
        }
    }

    // ---- bias + write out (both channels) ----
    #pragma unroll
    for (int n = 0; n < 4; ++n) {
        const size_t node = node0 + ng * 4 + n;
        #pragma unroll
        for (int m = 0; m < M_DIM; ++m) {
            float vlo = f2lo(acc2[n][m]);
            float vhi = f2hi(acc2[n][m]);
            if (m == 0) { vlo += bf_lo; vhi += bf_hi; }
            out[(node * M_DIM + m) * C_DIM + d5]      = vlo;
            out[(node * M_DIM + m) * C_DIM + d5 + 64] = vhi;
        }
    }
}

// ----------------------------------------------------------------------------
// Launch
// ----------------------------------------------------------------------------
extern "C" void kernel_launch(void* const* d_in, const int* in_sizes, int n_in,
                              void* d_out, int out_size)
{
    const float* x  = (const float*)d_in[0];
    const float* Wl = (const float*)d_in[1];
    const float* bl = (const float*)d_in[2];
    const float* Wr = (const float*)d_in[3];
    const float* br = (const float*)d_in[4];
    const float* Wf = (const float*)d_in[5];
    const float* bf = (const float*)d_in[6];
    float* out = (float*)d_out;

    W3J P;
    hw3j::build(P);

    cudaFuncSetAttribute(b2i_fused_kernel, cudaFuncAttributeMaxDynamicSharedMemorySize, SMEM_BYTES);

    b2i_fused_kernel<<<NNODES / B_NODES, THREADS, SMEM_BYTES>>>(
        x, Wl, bl, Wr, br, Wf, bf, out, P);
}

// round 5
// speedup vs baseline: 6.0037x; 6.0037x over previous
#include <cuda_runtime.h>
#include <cmath>
#include <complex>
#include <algorithm>

// ----------------------------------------------------------------------------
// Problem constants
// ----------------------------------------------------------------------------
#define NNODES   50000
#define C_DIM    128
#define M_DIM    9
#define B_NODES  8
#define THREADS  512

#define SX_F     (B_NODES * M_DIM * C_DIM)   // 9216 floats (x tile; later t tile)
#define SWA_ROW4 129                         // float4 per kpair row (128 + 1 pad)
#define SWA_F    (64 * SWA_ROW4 * 4)         // 33024 floats
#define SWC_ROW2 129                         // float2 per kpair row (128 + 1 pad)
#define SMEM_BYTES ((SX_F + SWA_F) * 4)      // 168960 B

typedef unsigned long long ull;

// Wigner-3j tables (alpha folded in), kernel arg.
struct W3J {
    float w220[25];
    float w121[45];
    float w112[45];
};

// ----------------------------------------------------------------------------
// Host-side Wigner 3j (literal translation of the reference, double precision)
// ----------------------------------------------------------------------------
namespace hw3j {
typedef std::complex<double> cd;

static inline double fact(int n) { double r = 1.0; for (int i = 2; i <= n; ++i) r *= (double)i; return r; }

static double su2_cg(int j1, int m1, int j2, int m2, int j3, int m3) {
    if (m1 + m2 != m3) return 0.0;
    int vmin = std::max(std::max(-j1 + j2 + m3, -j1 + m1), 0);
    int vmax = std::min(std::min(j2 + j3 + m1, j3 - j1 + j2), j3 + m3);
    double pref = std::sqrt((2.0 * j3 + 1.0)
        * fact(j3 + j1 - j2) * fact(j3 - j1 + j2) * fact(j1 + j2 - j3) / fact(j1 + j2 + j3 + 1)
        * fact(j3 + m3) * fact(j3 - m3)
        / (fact(j1 - m1) * fact(j1 + m1) * fact(j2 - m2) * fact(j2 + m2)));
    double s = 0.0;
    for (int v = vmin; v <= vmax; ++v) {
        double sgn = ((v + j2 + m2) & 1) ? -1.0 : 1.0;
        s += sgn / fact(v) * fact(j2 + j3 + m1 - v) * fact(j1 - m1 + v)
             / (fact(j3 - j1 + j2 - v) * fact(j3 + m3 - v) * fact(v + j1 - j2 - m3));
    }
    return pref * s;
}

static void qmat(int l, cd q[5][5]) {
    for (int a = 0; a < 5; ++a) for (int b = 0; b < 5; ++b) q[a][b] = cd(0, 0);
    const double is2 = 1.0 / std::sqrt(2.0);
    for (int m = -l; m < 0; ++m) {
        q[l + m][l - m] = cd(is2, 0.0);
        q[l + m][l + m] = cd(0.0, -is2);
    }
    q[l][l] = cd(1.0, 0.0);
    for (int m = 1; m <= l; ++m) {
        double sg = (m & 1) ? -1.0 : 1.0;
        q[l + m][l + m] = cd(sg * is2, 0.0);
        q[l + m][l - m] = cd(0.0, sg * is2);
    }
    cd ph;
    switch (l & 3) {
        case 0: ph = cd( 1,  0); break;
        case 1: ph = cd( 0, -1); break;
        case 2: ph = cd(-1,  0); break;
        default: ph = cd(0,  1); break;
    }
    for (int a = 0; a < 2 * l + 1; ++a) for (int b = 0; b < 2 * l + 1; ++b) q[a][b] *= ph;
}

static void wig3j(int l1, int l2, int l3, float* out) {
    const int d1 = 2 * l1 + 1, d2 = 2 * l2 + 1, d3 = 2 * l3 + 1;
    cd Q1[5][5], Q2[5][5], Q3[5][5];
    qmat(l1, Q1); qmat(l2, Q2); qmat(l3, Q3);
    static cd Csu2[5][5][5];
    for (int i = 0; i < d1; ++i)
        for (int k = 0; k < d2; ++k)
            for (int n = 0; n < d3; ++n)
                Csu2[i][k][n] = cd(su2_cg(l1, i - l1, l2, k - l2, l3, n - l3), 0.0);
    static double Cr[5][5][5];
    double nrm = 0.0;
    for (int j = 0; j < d1; ++j)
        for (int ll = 0; ll < d2; ++ll)
            for (int m = 0; m < d3; ++m) {
                cd acc(0, 0);
                for (int i = 0; i < d1; ++i)
                    for (int k = 0; k < d2; ++k)
                        for (int n = 0; n < d3; ++n)
                            acc += Q1[i][j] * Q2[k][ll] * std::conj(Q3[n][m]) * Csu2[i][k][n];
                Cr[j][ll][m] = acc.real();
                nrm += acc.real() * acc.real();
            }
    nrm = std::sqrt(nrm);
    int idx = 0;
    for (int j = 0; j < d1; ++j)
        for (int ll = 0; ll < d2; ++ll)
            for (int m = 0; m < d3; ++m)
                out[idx++] = (float)(Cr[j][ll][m] / nrm);
}

static void build(W3J& P) {
    float c220[25], c121[45], c112[45];
    wig3j(2, 2, 0, c220);
    wig3j(1, 2, 1, c121);
    wig3j(1, 1, 2, c112);
    const float a121 = std::sqrt(3.0f), a112 = std::sqrt(5.0f);
    for (int i = 0; i < 25; ++i) P.w220[i] = c220[i];
    for (int i = 0; i < 45; ++i) P.w121[i] = a121 * c121[i];
    for (int i = 0; i < 45; ++i) P.w112[i] = a112 * c112[i];
}
} // namespace hw3j

// ----------------------------------------------------------------------------
// Packed fp32 helpers
// ----------------------------------------------------------------------------
__device__ __forceinline__ void fma2(ull& acc, ull a, ull b) {
    asm("fma.rn.f32x2 %0, %1, %2, %0;" : "+l"(acc) : "l"(a), "l"(b));
}
__device__ __forceinline__ float f2lo(ull v) { return __uint_as_float((unsigned int)v); }
__device__ __forceinline__ float f2hi(ull v) { return __uint_as_float((unsigned int)(v >> 32)); }

// ----------------------------------------------------------------------------
// Compile-time stage helpers: all loop bounds / acc indices are constexpr so
// accumulators stay in registers (runtime 'l' indexing demotes them to local!)
// ----------------------------------------------------------------------------
template<int L>
__device__ __forceinline__ void stageA_compute(const float* __restrict__ sw,
                                               const float* __restrict__ sx,
                                               int s, int np,
                                               ull accL[2][M_DIM], ull accR[2][M_DIM])
{
    constexpr int base = L * L;
    constexpr int msz  = 2 * L + 1;
    const ulonglong2* sw4u = reinterpret_cast<const ulonglong2*>(sw);
    const ulonglong2* sx4u = reinterpret_cast<const ulonglong2*>(sx);
    #pragma unroll 4
    for (int q = 0; q < 32; ++q) {             // q = group of 4 k's (2 kpairs)
        const ulonglong2 w0 = sw4u[(2 * q)     * SWA_ROW4 + s]; // {Wl k0k1, Wr k0k1}
        const ulonglong2 w1 = sw4u[(2 * q + 1) * SWA_ROW4 + s]; // {Wl k2k3, Wr k2k3}
        #pragma unroll
        for (int n = 0; n < 2; ++n) {
            const int node = 2 * np + n;
            #pragma unroll
            for (int mm = 0; mm < msz; ++mm) {
                const ulonglong2 xv = sx4u[(node * M_DIM + base + mm) * 32 + q]; // broadcast
                fma2(accL[n][base + mm], xv.x, w0.x);
                fma2(accR[n][base + mm], xv.x, w0.y);
                fma2(accL[n][base + mm], xv.y, w1.x);
                fma2(accR[n][base + mm], xv.y, w1.y);
            }
        }
    }
}

template<int L>
__device__ __forceinline__ void stageC_compute(const float* __restrict__ sw,
                                               const float* __restrict__ st,
                                               int s, int np,
                                               ull acc2[2][M_DIM])
{
    constexpr int base = L * L;
    constexpr int msz  = 2 * L + 1;
    const ull* sw2u = reinterpret_cast<const ull*>(sw);
    const ulonglong2* st4u = reinterpret_cast<const ulonglong2*>(st);
    #pragma unroll 4
    for (int q = 0; q < 32; ++q) {
        const ull w0 = sw2u[(2 * q)     * SWC_ROW2 + s];
        const ull w1 = sw2u[(2 * q + 1) * SWC_ROW2 + s];
        #pragma unroll
        for (int n = 0; n < 2; ++n) {
            const int node = 2 * np + n;
            #pragma unroll
            for (int mm = 0; mm < msz; ++mm) {
                const ulonglong2 tv = st4u[(node * M_DIM + base + mm) * 32 + q]; // broadcast
                fma2(acc2[n][base + mm], tv.x, w0);
                fma2(acc2[n][base + mm], tv.y, w1);
            }
        }
    }
}

// ----------------------------------------------------------------------------
// Fused kernel. 512 threads:
//   np = warp & 3                -> node pair {2np, 2np+1} of the 8-node tile
//   s  = lane + 32*(warp>>2)     -> channel 0..127
// f32x2 packing = {even-k partial, odd-k partial}, merged at stage end.
// ----------------------------------------------------------------------------
__global__ __launch_bounds__(THREADS, 1)
void b2i_fused_kernel(const float* __restrict__ x,
                      const float* __restrict__ Wl, const float* __restrict__ bl,
                      const float* __restrict__ Wr, const float* __restrict__ br,
                      const float* __restrict__ Wf, const float* __restrict__ bf,
                      float* __restrict__ out, const W3J P)
{
    extern __shared__ float smem[];
    float* sx = smem;            // x tile [8][9][128]; later t tile
    float* sw = smem + SX_F;     // weight staging

    const int tid  = threadIdx.x;
    const int lane = tid & 31;
    const int warp = tid >> 5;
    const int np   = warp & 3;
    const int s    = lane + ((warp >> 2) << 5);
    const size_t node0 = (size_t)blockIdx.x * B_NODES;

    // ---- load x tile (coalesced float2) ----
    {
        const float2* gx = reinterpret_cast<const float2*>(x + node0 * M_DIM * C_DIM);
        float2* sx2 = reinterpret_cast<float2*>(sx);
        #pragma unroll
        for (int i = 0; i < (SX_F / 2) / THREADS; ++i)
            sx2[tid + i * THREADS] = gx[tid + i * THREADS];
    }

    const float blv = bl[s];
    const float brv = br[s];
    const float bfv = bf[s];

    // =========================================================================
    // Stage A: yl/yr linears (k-parity packed)
    // =========================================================================
    ull accL[2][M_DIM], accR[2][M_DIM];
    #pragma unroll
    for (int n = 0; n < 2; ++n)
        #pragma unroll
        for (int m = 0; m < M_DIM; ++m) { accL[n][m] = 0ULL; accR[n][m] = 0ULL; }

    #pragma unroll
    for (int l = 0; l < 3; ++l) {
        __syncthreads();   // x ready (l=0) / prev-l compute done reading sw
        // ---- stage Wl/Wr: sw4[kp][ss] = {Wl[ss][2kp],Wl[ss][2kp+1],Wr[ss][2kp],Wr[ss][2kp+1]} ----
        {
            float4* sw4 = reinterpret_cast<float4*>(sw);
            #pragma unroll
            for (int i = 0; i < 16; ++i) {
                const int idx = tid + i * THREADS;     // 0..8191
                const int kp = idx & 63;
                const int ss = idx >> 6;
                const float2 a = __ldg(reinterpret_cast<const float2*>(Wl + (size_t)(l * 128 + ss) * 128 + kp * 2));
                const float2 b = __ldg(reinterpret_cast<const float2*>(Wr + (size_t)(l * 128 + ss) * 128 + kp * 2));
                sw4[kp * SWA_ROW4 + ss] = make_float4(a.x, a.y, b.x, b.y);
            }
        }
        __syncthreads();
        if (l == 0)      stageA_compute<0>(sw, sx, s, np, accL, accR);
        else if (l == 1) stageA_compute<1>(sw, sx, s, np, accL, accR);
        else             stageA_compute<2>(sw, sx, s, np, accL, accR);
    }

    // =========================================================================
    // Stage B: merge parities, bias, CG tensor product -> t into sx region
    // =========================================================================
    __syncthreads();   // all stage-A reads of sx complete
    float* st = sx;
    #pragma unroll
    for (int n = 0; n < 2; ++n) {
        const int node = 2 * np + n;
        float L[M_DIM], R[M_DIM];
        #pragma unroll
        for (int m = 0; m < M_DIM; ++m) {
            L[m] = f2lo(accL[n][m]) + f2hi(accL[n][m]);
            R[m] = f2lo(accR[n][m]) + f2hi(accR[n][m]);
        }
        L[0] += blv; R[0] += brv;

        float t[M_DIM];
        {   // (2,2,0)
            float v = 0.f;
            #pragma unroll
            for (int i = 0; i < 5; ++i)
                #pragma unroll
                for (int j = 0; j < 5; ++j)
                    v = fmaf(P.w220[i * 5 + j], L[4 + i] * R[4 + j], v);
            t[0] = v;
        }
        #pragma unroll
        for (int k = 0; k < 3; ++k) {   // (1,2,1)
            float v = 0.f;
            #pragma unroll
            for (int i = 0; i < 3; ++i)
                #pragma unroll
                for (int j = 0; j < 5; ++j)
                    v = fmaf(P.w121[(i * 5 + j) * 3 + k], L[1 + i] * R[4 + j], v);
            t[1 + k] = v;
        }
        #pragma unroll
        for (int k = 0; k < 5; ++k) {   // (1,1,2)
            float v = 0.f;
            #pragma unroll
            for (int i = 0; i < 3; ++i)
                #pragma unroll
                for (int j = 0; j < 3; ++j)
                    v = fmaf(P.w112[(i * 3 + j) * 5 + k], L[1 + i] * R[1 + j], v);
            t[4 + k] = v;
        }
        #pragma unroll
        for (int m = 0; m < M_DIM; ++m)
            st[(node * M_DIM + m) * C_DIM + s] = t[m];
    }

    // =========================================================================
    // Stage C: final linear over t (k-parity packed)
    // =========================================================================
    ull acc2[2][M_DIM];
    #pragma unroll
    for (int n = 0; n < 2; ++n)
        #pragma unroll
        for (int m = 0; m < M_DIM; ++m) acc2[n][m] = 0ULL;

    #pragma unroll
    for (int l = 0; l < 3; ++l) {
        __syncthreads();   // t writes done (l=0) / prev-l compute done
        // ---- stage Wf[l]: sw2[kp][ss] = {Wf[ss][2kp], Wf[ss][2kp+1]} ----
        {
            float2* sw2 = reinterpret_cast<float2*>(sw);
            #pragma unroll
            for (int i = 0; i < 16; ++i) {
                const int idx = tid + i * THREADS;
                const int kp = idx & 63;
                const int ss = idx >> 6;
                sw2[kp * SWC_ROW2 + ss] =
                    __ldg(reinterpret_cast<const float2*>(Wf + (size_t)(l * 128 + ss) * 128 + kp * 2));
            }
        }
        __syncthreads();
        if (l == 0)      stageC_compute<0>(sw, st, s, np, acc2);
        else if (l == 1) stageC_compute<1>(sw, st, s, np, acc2);
        else             stageC_compute<2>(sw, st, s, np, acc2);
    }

    // ---- merge, bias, write out ----
    #pragma unroll
    for (int n = 0; n < 2; ++n) {
        const size_t node = node0 + 2 * np + n;
        #pragma unroll
        for (int m = 0; m < M_DIM; ++m) {
            float v = f2lo(acc2[n][m]) + f2hi(acc2[n][m]);
            if (m == 0) v += bfv;
            out[(node * M_DIM + m) * C_DIM + s] = v;
        }
    }
}

// ----------------------------------------------------------------------------
// Launch
// ----------------------------------------------------------------------------
extern "C" void kernel_launch(void* const* d_in, const int* in_sizes, int n_in,
                              void* d_out, int out_size)
{
    const float* x  = (const float*)d_in[0];
    const float* Wl = (const float*)d_in[1];
    const float* bl = (const float*)d_in[2];
    const float* Wr = (const float*)d_in[3];
    const float* br = (const float*)d_in[4];
    const float* Wf = (const float*)d_in[5];
    const float* bf = (const float*)d_in[6];
    float* out = (float*)d_out;

    W3J P;
    hw3j::build(P);

    cudaFuncSetAttribute(b2i_fused_kernel, cudaFuncAttributeMaxDynamicSharedMemorySize, SMEM_BYTES);

    b2i_fused_kernel<<<NNODES / B_NODES, THREADS, SMEM_BYTES>>>(
        x, Wl, bl, Wr, br, Wf, bf, out, P);
}

// round 6
// speedup vs baseline: 8.0644x; 1.3432x over previous
#include <cuda_runtime.h>
#include <cmath>
#include <complex>
#include <algorithm>

// ----------------------------------------------------------------------------
// Problem constants
// ----------------------------------------------------------------------------
#define NNODES   50000
#define C_DIM    128
#define M_DIM    9
#define B_NODES  16
#define THREADS  512
#define STRIDE   132                       // smem row stride in floats (==4 mod 32)

#define SX_F   (144 * STRIDE)              // 19008 floats: x rows [m*16+node][c]; later t
#define SW_F   (128 * STRIDE)              // 16896 floats per weight matrix
#define SMEM_BYTES ((SX_F + 2 * SW_F) * 4) // 211200 B

// Wigner-3j tables (alpha folded in), kernel arg.
struct W3J {
    float w220[25];
    float w121[45];
    float w112[45];
};

// ----------------------------------------------------------------------------
// Host-side Wigner 3j (literal translation of the reference, double precision)
// ----------------------------------------------------------------------------
namespace hw3j {
typedef std::complex<double> cd;

static inline double fact(int n) { double r = 1.0; for (int i = 2; i <= n; ++i) r *= (double)i; return r; }

static double su2_cg(int j1, int m1, int j2, int m2, int j3, int m3) {
    if (m1 + m2 != m3) return 0.0;
    int vmin = std::max(std::max(-j1 + j2 + m3, -j1 + m1), 0);
    int vmax = std::min(std::min(j2 + j3 + m1, j3 - j1 + j2), j3 + m3);
    double pref = std::sqrt((2.0 * j3 + 1.0)
        * fact(j3 + j1 - j2) * fact(j3 - j1 + j2) * fact(j1 + j2 - j3) / fact(j1 + j2 + j3 + 1)
        * fact(j3 + m3) * fact(j3 - m3)
        / (fact(j1 - m1) * fact(j1 + m1) * fact(j2 - m2) * fact(j2 + m2)));
    double s = 0.0;
    for (int v = vmin; v <= vmax; ++v) {
        double sgn = ((v + j2 + m2) & 1) ? -1.0 : 1.0;
        s += sgn / fact(v) * fact(j2 + j3 + m1 - v) * fact(j1 - m1 + v)
             / (fact(j3 - j1 + j2 - v) * fact(j3 + m3 - v) * fact(v + j1 - j2 - m3));
    }
    return pref * s;
}

static void qmat(int l, cd q[5][5]) {
    for (int a = 0; a < 5; ++a) for (int b = 0; b < 5; ++b) q[a][b] = cd(0, 0);
    const double is2 = 1.0 / std::sqrt(2.0);
    for (int m = -l; m < 0; ++m) {
        q[l + m][l - m] = cd(is2, 0.0);
        q[l + m][l + m] = cd(0.0, -is2);
    }
    q[l][l] = cd(1.0, 0.0);
    for (int m = 1; m <= l; ++m) {
        double sg = (m & 1) ? -1.0 : 1.0;
        q[l + m][l + m] = cd(sg * is2, 0.0);
        q[l + m][l - m] = cd(0.0, sg * is2);
    }
    cd ph;
    switch (l & 3) {
        case 0: ph = cd( 1,  0); break;
        case 1: ph = cd( 0, -1); break;
        case 2: ph = cd(-1,  0); break;
        default: ph = cd(0,  1); break;
    }
    for (int a = 0; a < 2 * l + 1; ++a) for (int b = 0; b < 2 * l + 1; ++b) q[a][b] *= ph;
}

static void wig3j(int l1, int l2, int l3, float* out) {
    const int d1 = 2 * l1 + 1, d2 = 2 * l2 + 1, d3 = 2 * l3 + 1;
    cd Q1[5][5], Q2[5][5], Q3[5][5];
    qmat(l1, Q1); qmat(l2, Q2); qmat(l3, Q3);
    static cd Csu2[5][5][5];
    for (int i = 0; i < d1; ++i)
        for (int k = 0; k < d2; ++k)
            for (int n = 0; n < d3; ++n)
                Csu2[i][k][n] = cd(su2_cg(l1, i - l1, l2, k - l2, l3, n - l3), 0.0);
    static double Cr[5][5][5];
    double nrm = 0.0;
    for (int j = 0; j < d1; ++j)
        for (int ll = 0; ll < d2; ++ll)
            for (int m = 0; m < d3; ++m) {
                cd acc(0, 0);
                for (int i = 0; i < d1; ++i)
                    for (int k = 0; k < d2; ++k)
                        for (int n = 0; n < d3; ++n)
                            acc += Q1[i][j] * Q2[k][ll] * std::conj(Q3[n][m]) * Csu2[i][k][n];
                Cr[j][ll][m] = acc.real();
                nrm += acc.real() * acc.real();
            }
    nrm = std::sqrt(nrm);
    int idx = 0;
    for (int j = 0; j < d1; ++j)
        for (int ll = 0; ll < d2; ++ll)
            for (int m = 0; m < d3; ++m)
                out[idx++] = (float)(Cr[j][ll][m] / nrm);
}

static void build(W3J& P) {
    float c220[25], c121[45], c112[45];
    wig3j(2, 2, 0, c220);
    wig3j(1, 2, 1, c121);
    wig3j(1, 1, 2, c112);
    const float a121 = std::sqrt(3.0f), a112 = std::sqrt(5.0f);
    for (int i = 0; i < 25; ++i) P.w220[i] = c220[i];
    for (int i = 0; i < 45; ++i) P.w121[i] = a121 * c121[i];
    for (int i = 0; i < 45; ++i) P.w112[i] = a112 * c112[i];
}
} // namespace hw3j

// ----------------------------------------------------------------------------
// tf32 helpers
// ----------------------------------------------------------------------------
__device__ __forceinline__ unsigned tf32_of(float x) {
    unsigned r;
    asm("cvt.rna.tf32.f32 %0, %1;" : "=r"(r) : "f"(x));
    return r;
}
__device__ __forceinline__ void tf32_split(float x, unsigned& hi, unsigned& lo) {
    hi = tf32_of(x);
    lo = tf32_of(x - __uint_as_float(hi));
}
__device__ __forceinline__ void mma8(float (&d)[4], const unsigned (&a)[4], const unsigned (&b)[2]) {
    asm("mma.sync.aligned.m16n8k8.row.col.f32.tf32.tf32.f32 "
        "{%0,%1,%2,%3}, {%4,%5,%6,%7}, {%8,%9}, {%0,%1,%2,%3};"
        : "+f"(d[0]), "+f"(d[1]), "+f"(d[2]), "+f"(d[3])
        : "r"(a[0]), "r"(a[1]), "r"(a[2]), "r"(a[3]), "r"(b[0]), "r"(b[1]));
}

// Load + 3xTF32-split an A fragment (rows m-tile, k-step s) from smem.
__device__ __forceinline__ void load_a_frag(const float* __restrict__ sA, int row_base,
                                            int g, int tg, int s,
                                            unsigned (&ah)[4], unsigned (&al)[4]) {
    const float* r0 = sA + (row_base + g)     * STRIDE + 8 * s + tg;
    const float* r1 = sA + (row_base + g + 8) * STRIDE + 8 * s + tg;
    float a0 = r0[0], a1 = r1[0], a2 = r0[4], a3 = r1[4];
    tf32_split(a0, ah[0], al[0]);
    tf32_split(a1, ah[1], al[1]);
    tf32_split(a2, ah[2], al[2]);
    tf32_split(a3, ah[3], al[3]);
}

// Load + split a B fragment (channels 8*nt.., k-step s) from smem weight matrix.
__device__ __forceinline__ void load_b_frag(const float* __restrict__ sB, int nt,
                                            int g, int tg, int s,
                                            unsigned (&bh)[2], unsigned (&bl)[2]) {
    const float* r = sB + (8 * nt + g) * STRIDE + 8 * s + tg;
    float b0 = r[0], b1 = r[4];
    tf32_split(b0, bh[0], bl[0]);
    tf32_split(b1, bh[1], bl[1]);
}

// ----------------------------------------------------------------------------
// Per-degree mma stages (compile-time L so accumulator indices stay literal)
// ----------------------------------------------------------------------------
template<int L>
__device__ __forceinline__ void stageA_mma(const float* __restrict__ sx,
                                           const float* __restrict__ swl,
                                           const float* __restrict__ swr,
                                           int nt, int g, int tg,
                                           float (&yL)[M_DIM][4], float (&yR)[M_DIM][4]) {
    constexpr int base = L * L;
    constexpr int msz  = 2 * L + 1;
    #pragma unroll 2
    for (int s = 0; s < 16; ++s) {
        unsigned bLh[2], bLl[2], bRh[2], bRl[2];
        load_b_frag(swl, nt, g, tg, s, bLh, bLl);
        load_b_frag(swr, nt, g, tg, s, bRh, bRl);
        #pragma unroll
        for (int ml = 0; ml < msz; ++ml) {
            unsigned ah[4], al[4];
            load_a_frag(sx, (base + ml) * 16, g, tg, s, ah, al);
            mma8(yL[base + ml], ah, bLh);
            mma8(yL[base + ml], ah, bLl);
            mma8(yL[base + ml], al, bLh);
            mma8(yR[base + ml], ah, bRh);
            mma8(yR[base + ml], ah, bRl);
            mma8(yR[base + ml], al, bRh);
        }
    }
}

template<int L>
__device__ __forceinline__ void stageC_mma(const float* __restrict__ st,
                                           const float* __restrict__ swf,
                                           int nt, int g, int tg,
                                           float (&fo)[M_DIM][4]) {
    constexpr int base = L * L;
    constexpr int msz  = 2 * L + 1;
    #pragma unroll 2
    for (int s = 0; s < 16; ++s) {
        unsigned bh[2], bl[2];
        load_b_frag(swf, nt, g, tg, s, bh, bl);
        #pragma unroll
        for (int ml = 0; ml < msz; ++ml) {
            unsigned ah[4], al[4];
            load_a_frag(st, (base + ml) * 16, g, tg, s, ah, al);
            mma8(fo[base + ml], ah, bh);
            mma8(fo[base + ml], ah, bl);
            mma8(fo[base + ml], al, bh);
        }
    }
}

// CG tensor product for one (node, channel): L[9], R[9] -> t[9]
__device__ __forceinline__ void tp_compute(const float (&L)[M_DIM], const float (&R)[M_DIM],
                                           float (&t)[M_DIM], const W3J& P) {
    {   // (2,2,0)
        float v = 0.f;
        #pragma unroll
        for (int i = 0; i < 5; ++i)
            #pragma unroll
            for (int j = 0; j < 5; ++j)
                v = fmaf(P.w220[i * 5 + j], L[4 + i] * R[4 + j], v);
        t[0] = v;
    }
    #pragma unroll
    for (int k = 0; k < 3; ++k) {   // (1,2,1)
        float v = 0.f;
        #pragma unroll
        for (int i = 0; i < 3; ++i)
            #pragma unroll
            for (int j = 0; j < 5; ++j)
                v = fmaf(P.w121[(i * 5 + j) * 3 + k], L[1 + i] * R[4 + j], v);
        t[1 + k] = v;
    }
    #pragma unroll
    for (int k = 0; k < 5; ++k) {   // (1,1,2)
        float v = 0.f;
        #pragma unroll
        for (int i = 0; i < 3; ++i)
            #pragma unroll
            for (int j = 0; j < 3; ++j)
                v = fmaf(P.w112[(i * 3 + j) * 5 + k], L[1 + i] * R[1 + j], v);
        t[4 + k] = v;
    }
}

// ----------------------------------------------------------------------------
// Fused kernel. 512 threads = 16 warps; warp nt owns output channels [8nt, 8nt+8).
// GEMM rows ordered as (m*16 + node) so each m is its own 16-row M-tile and the
// tensor product is thread-local on accumulator fragments.
// ----------------------------------------------------------------------------
__global__ __launch_bounds__(THREADS, 1)
void b2i_mma_kernel(const float* __restrict__ x,
                    const float* __restrict__ Wl, const float* __restrict__ bl,
                    const float* __restrict__ Wr, const float* __restrict__ br,
                    const float* __restrict__ Wf, const float* __restrict__ bf,
                    float* __restrict__ out, const W3J P)
{
    extern __shared__ float smem[];
    float* sx  = smem;                 // [144][STRIDE] x rows (m*16+node); later t
    float* swl = smem + SX_F;          // [128][STRIDE] Wl_l / Wf_l
    float* swr = smem + SX_F + SW_F;   // [128][STRIDE] Wr_l

    const int tid  = threadIdx.x;
    const int lane = tid & 31;
    const int nt   = tid >> 5;         // warp id = channel tile
    const int g    = lane >> 2;        // groupID
    const int tg   = lane & 3;         // thread in group
    const size_t node0 = (size_t)blockIdx.x * B_NODES;

    // ---- stage x tile: global [node][m][c] -> smem row (m*16+node), stride 132 ----
    {
        #pragma unroll
        for (int i = 0; i < 9; ++i) {
            const int idx = tid + i * THREADS;     // 0..4607 float4s
            const int row = idx >> 5;              // 0..143 = node*9+m
            const int c4  = idx & 31;
            const int node = (row * 57) >> 9;      // row / 9 for row<144
            const int m    = row - node * 9;
            const float4 v = __ldg(reinterpret_cast<const float4*>(
                x + ((node0 + node) * M_DIM + m) * C_DIM + c4 * 4));
            *reinterpret_cast<float4*>(sx + (m * 16 + node) * STRIDE + c4 * 4) = v;
        }
    }

    // =========================================================================
    // Stage A: y_l / y_r via 3xTF32 mma, accumulated in fragments
    // =========================================================================
    float yL[M_DIM][4], yR[M_DIM][4];
    #pragma unroll
    for (int m = 0; m < M_DIM; ++m)
        #pragma unroll
        for (int c = 0; c < 4; ++c) { yL[m][c] = 0.f; yR[m][c] = 0.f; }

    #pragma unroll
    for (int l = 0; l < 3; ++l) {
        __syncthreads();   // x ready (l=0) / prev-l mma done reading sw
        {   // stage Wl_l, Wr_l (row d, stride 132)
            #pragma unroll
            for (int i = 0; i < 8; ++i) {
                const int idx = tid + i * THREADS;   // 0..4095
                const int row = idx >> 5;
                const int c4  = idx & 31;
                const float4 a = __ldg(reinterpret_cast<const float4*>(
                    Wl + (size_t)(l * 128 + row) * 128 + c4 * 4));
                const float4 b = __ldg(reinterpret_cast<const float4*>(
                    Wr + (size_t)(l * 128 + row) * 128 + c4 * 4));
                *reinterpret_cast<float4*>(swl + row * STRIDE + c4 * 4) = a;
                *reinterpret_cast<float4*>(swr + row * STRIDE + c4 * 4) = b;
            }
        }
        __syncthreads();
        if (l == 0)      stageA_mma<0>(sx, swl, swr, nt, g, tg, yL, yR);
        else if (l == 1) stageA_mma<1>(sx, swl, swr, nt, g, tg, yL, yR);
        else             stageA_mma<2>(sx, swl, swr, nt, g, tg, yL, yR);
    }

    __syncthreads();   // all mma reads of sx complete before t overwrites it

    // =========================================================================
    // Stage B: thread-local tensor product on fragments, t -> smem (sx region)
    // Thread owns combos: (node g,   ch 8nt+2tg)   = frag idx 0
    //                     (node g,   ch 8nt+2tg+1) = frag idx 1
    //                     (node g+8, ch 8nt+2tg)   = frag idx 2
    //                     (node g+8, ch 8nt+2tg+1) = frag idx 3
    // =========================================================================
    float* st = sx;
    {
        const int ch0 = 8 * nt + 2 * tg;
        const float bl0 = bl[ch0], bl1 = bl[ch0 + 1];
        const float br0 = br[ch0], br1 = br[ch0 + 1];

        float La[M_DIM], Ra[M_DIM], Lb[M_DIM], Rb[M_DIM], ta[M_DIM], tb[M_DIM];

        // node g (frag slots 0,1)
        #pragma unroll
        for (int m = 0; m < M_DIM; ++m) {
            La[m] = yL[m][0]; Ra[m] = yR[m][0];
            Lb[m] = yL[m][1]; Rb[m] = yR[m][1];
        }
        La[0] += bl0; Ra[0] += br0; Lb[0] += bl1; Rb[0] += br1;
        tp_compute(La, Ra, ta, P);
        tp_compute(Lb, Rb, tb, P);
        #pragma unroll
        for (int m = 0; m < M_DIM; ++m)
            *reinterpret_cast<float2*>(st + (m * 16 + g) * STRIDE + ch0) =
                make_float2(ta[m], tb[m]);

        // node g+8 (frag slots 2,3)
        #pragma unroll
        for (int m = 0; m < M_DIM; ++m) {
            La[m] = yL[m][2]; Ra[m] = yR[m][2];
            Lb[m] = yL[m][3]; Rb[m] = yR[m][3];
        }
        La[0] += bl0; Ra[0] += br0; Lb[0] += bl1; Rb[0] += br1;
        tp_compute(La, Ra, ta, P);
        tp_compute(Lb, Rb, tb, P);
        #pragma unroll
        for (int m = 0; m < M_DIM; ++m)
            *reinterpret_cast<float2*>(st + (m * 16 + g + 8) * STRIDE + ch0) =
                make_float2(ta[m], tb[m]);
    }

    // =========================================================================
    // Stage C: final linear via 3xTF32 mma (t fragments from smem)
    // =========================================================================
    float fo[M_DIM][4];
    #pragma unroll
    for (int m = 0; m < M_DIM; ++m)
        #pragma unroll
        for (int c = 0; c < 4; ++c) fo[m][c] = 0.f;

    #pragma unroll
    for (int l = 0; l < 3; ++l) {
        __syncthreads();   // t stores done (l=0) / prev-l mma done reading swl
        {   // stage Wf_l into swl
            #pragma unroll
            for (int i = 0; i < 8; ++i) {
                const int idx = tid + i * THREADS;
                const int row = idx >> 5;
                const int c4  = idx & 31;
                const float4 a = __ldg(reinterpret_cast<const float4*>(
                    Wf + (size_t)(l * 128 + row) * 128 + c4 * 4));
                *reinterpret_cast<float4*>(swl + row * STRIDE + c4 * 4) = a;
            }
        }
        __syncthreads();
        if (l == 0)      stageC_mma<0>(st, swl, nt, g, tg, fo);
        else if (l == 1) stageC_mma<1>(st, swl, nt, g, tg, fo);
        else             stageC_mma<2>(st, swl, nt, g, tg, fo);
    }

    // ---- bias + write out: frag (row=m*16+node, col=channel) -> out[node][m][d] ----
    {
        const int ch0 = 8 * nt + 2 * tg;
        const float bf0 = bf[ch0], bf1 = bf[ch0 + 1];
        #pragma unroll
        for (int m = 0; m < M_DIM; ++m) {
            float v0 = fo[m][0], v1 = fo[m][1], v2 = fo[m][2], v3 = fo[m][3];
            if (m == 0) { v0 += bf0; v1 += bf1; v2 += bf0; v3 += bf1; }
            const size_t nA = node0 + g;
            const size_t nB = node0 + g + 8;
            *reinterpret_cast<float2*>(out + (nA * M_DIM + m) * C_DIM + ch0) =
                make_float2(v0, v1);
            *reinterpret_cast<float2*>(out + (nB * M_DIM + m) * C_DIM + ch0) =
                make_float2(v2, v3);
        }
    }
}

// ----------------------------------------------------------------------------
// Launch
// ----------------------------------------------------------------------------
extern "C" void kernel_launch(void* const* d_in, const int* in_sizes, int n_in,
                              void* d_out, int out_size)
{
    const float* x  = (const float*)d_in[0];
    const float* Wl = (const float*)d_in[1];
    const float* bl = (const float*)d_in[2];
    const float* Wr = (const float*)d_in[3];
    const float* br = (const float*)d_in[4];
    const float* Wf = (const float*)d_in[5];
    const float* bf = (const float*)d_in[6];
    float* out = (float*)d_out;

    W3J P;
    hw3j::build(P);

    cudaFuncSetAttribute(b2i_mma_kernel, cudaFuncAttributeMaxDynamicSharedMemorySize, SMEM_BYTES);

    b2i_mma_kernel<<<NNODES / B_NODES, THREADS, SMEM_BYTES>>>(
        x, Wl, bl, Wr, br, Wf, bf, out, P);
}

// round 7
// speedup vs baseline: 15.5649x; 1.9301x over previous
#include <cuda_runtime.h>
#include <cmath>
#include <complex>
#include <algorithm>

// ----------------------------------------------------------------------------
// Problem constants
// ----------------------------------------------------------------------------
#define NNODES   50000
#define C_DIM    128
#define M_DIM    9
#define B_NODES  16
#define THREADS  512

// Word (b32 = bf16x2) layouts
#define KW       64                        // b32 words per 128-bf16 row
#define XSTRIDE  68                        // row stride in words (==4 mod 32)
#define SXW      (144 * XSTRIDE)           // 9792 words per x part (hi or lo)
#define SWW      (128 * XSTRIDE)           // 8704 words per weight part

// smem word offsets
#define OFF_XH   0
#define OFF_XL   (SXW)
#define OFF_WLH  (2 * SXW)
#define OFF_WLL  (2 * SXW + SWW)
#define OFF_WRH  (2 * SXW + 2 * SWW)
#define OFF_WRL  (2 * SXW + 3 * SWW)
#define SMEM_WORDS (2 * SXW + 4 * SWW)     // 54400 words
#define SMEM_BYTES (SMEM_WORDS * 4)        // 217600 B

// Wigner-3j tables (alpha folded in), kernel arg.
struct W3J {
    float w220[25];
    float w121[45];
    float w112[45];
};

// ----------------------------------------------------------------------------
// Host-side Wigner 3j (literal translation of the reference, double precision)
// ----------------------------------------------------------------------------
namespace hw3j {
typedef std::complex<double> cd;

static inline double fact(int n) { double r = 1.0; for (int i = 2; i <= n; ++i) r *= (double)i; return r; }

static double su2_cg(int j1, int m1, int j2, int m2, int j3, int m3) {
    if (m1 + m2 != m3) return 0.0;
    int vmin = std::max(std::max(-j1 + j2 + m3, -j1 + m1), 0);
    int vmax = std::min(std::min(j2 + j3 + m1, j3 - j1 + j2), j3 + m3);
    double pref = std::sqrt((2.0 * j3 + 1.0)
        * fact(j3 + j1 - j2) * fact(j3 - j1 + j2) * fact(j1 + j2 - j3) / fact(j1 + j2 + j3 + 1)
        * fact(j3 + m3) * fact(j3 - m3)
        / (fact(j1 - m1) * fact(j1 + m1) * fact(j2 - m2) * fact(j2 + m2)));
    double s = 0.0;
    for (int v = vmin; v <= vmax; ++v) {
        double sgn = ((v + j2 + m2) & 1) ? -1.0 : 1.0;
        s += sgn / fact(v) * fact(j2 + j3 + m1 - v) * fact(j1 - m1 + v)
             / (fact(j3 - j1 + j2 - v) * fact(j3 + m3 - v) * fact(v + j1 - j2 - m3));
    }
    return pref * s;
}

static void qmat(int l, cd q[5][5]) {
    for (int a = 0; a < 5; ++a) for (int b = 0; b < 5; ++b) q[a][b] = cd(0, 0);
    const double is2 = 1.0 / std::sqrt(2.0);
    for (int m = -l; m < 0; ++m) {
        q[l + m][l - m] = cd(is2, 0.0);
        q[l + m][l + m] = cd(0.0, -is2);
    }
    q[l][l] = cd(1.0, 0.0);
    for (int m = 1; m <= l; ++m) {
        double sg = (m & 1) ? -1.0 : 1.0;
        q[l + m][l + m] = cd(sg * is2, 0.0);
        q[l + m][l - m] = cd(0.0, sg * is2);
    }
    cd ph;
    switch (l & 3) {
        case 0: ph = cd( 1,  0); break;
        case 1: ph = cd( 0, -1); break;
        case 2: ph = cd(-1,  0); break;
        default: ph = cd(0,  1); break;
    }
    for (int a = 0; a < 2 * l + 1; ++a) for (int b = 0; b < 2 * l + 1; ++b) q[a][b] *= ph;
}

static void wig3j(int l1, int l2, int l3, float* out) {
    const int d1 = 2 * l1 + 1, d2 = 2 * l2 + 1, d3 = 2 * l3 + 1;
    cd Q1[5][5], Q2[5][5], Q3[5][5];
    qmat(l1, Q1); qmat(l2, Q2); qmat(l3, Q3);
    static cd Csu2[5][5][5];
    for (int i = 0; i < d1; ++i)
        for (int k = 0; k < d2; ++k)
            for (int n = 0; n < d3; ++n)
                Csu2[i][k][n] = cd(su2_cg(l1, i - l1, l2, k - l2, l3, n - l3), 0.0);
    static double Cr[5][5][5];
    double nrm = 0.0;
    for (int j = 0; j < d1; ++j)
        for (int ll = 0; ll < d2; ++ll)
            for (int m = 0; m < d3; ++m) {
                cd acc(0, 0);
                for (int i = 0; i < d1; ++i)
                    for (int k = 0; k < d2; ++k)
                        for (int n = 0; n < d3; ++n)
                            acc += Q1[i][j] * Q2[k][ll] * std::conj(Q3[n][m]) * Csu2[i][k][n];
                Cr[j][ll][m] = acc.real();
                nrm += acc.real() * acc.real();
            }
    nrm = std::sqrt(nrm);
    int idx = 0;
    for (int j = 0; j < d1; ++j)
        for (int ll = 0; ll < d2; ++ll)
            for (int m = 0; m < d3; ++m)
                out[idx++] = (float)(Cr[j][ll][m] / nrm);
}

static void build(W3J& P) {
    float c220[25], c121[45], c112[45];
    wig3j(2, 2, 0, c220);
    wig3j(1, 2, 1, c121);
    wig3j(1, 1, 2, c112);
    const float a121 = std::sqrt(3.0f), a112 = std::sqrt(5.0f);
    for (int i = 0; i < 25; ++i) P.w220[i] = c220[i];
    for (int i = 0; i < 45; ++i) P.w121[i] = a121 * c121[i];
    for (int i = 0; i < 45; ++i) P.w112[i] = a112 * c112[i];
}
} // namespace hw3j

// ----------------------------------------------------------------------------
// bf16 split helpers
// ----------------------------------------------------------------------------
// pack two floats into bf16x2 word: low half = e0, high half = e1
__device__ __forceinline__ unsigned pack_bf16(float e0, float e1) {
    unsigned r;
    asm("cvt.rn.bf16x2.f32 %0, %1, %2;" : "=r"(r) : "f"(e1), "f"(e0));
    return r;
}
// split pair (e0,e1) into hi word + lo (residual) word
__device__ __forceinline__ void split_pair(float e0, float e1, unsigned& hi, unsigned& lo) {
    hi = pack_bf16(e0, e1);
    const float h0 = __uint_as_float(hi << 16);
    const float h1 = __uint_as_float(hi & 0xffff0000u);
    lo = pack_bf16(e0 - h0, e1 - h1);
}

__device__ __forceinline__ void mma16(float (&d)[4], const unsigned (&a)[4], const unsigned (&b)[2]) {
    asm("mma.sync.aligned.m16n8k16.row.col.f32.bf16.bf16.f32 "
        "{%0,%1,%2,%3}, {%4,%5,%6,%7}, {%8,%9}, {%0,%1,%2,%3};"
        : "+f"(d[0]), "+f"(d[1]), "+f"(d[2]), "+f"(d[3])
        : "r"(a[0]), "r"(a[1]), "r"(a[2]), "r"(a[3]), "r"(b[0]), "r"(b[1]));
}

// Load A frag (4 words) for m-tile row_base, k-step s, from a split array.
__device__ __forceinline__ void load_a(const unsigned* __restrict__ sA, int row_base,
                                       int g, int tg, int s, unsigned (&a)[4]) {
    const unsigned* r0 = sA + (row_base + g)     * XSTRIDE + 8 * s + tg;
    const unsigned* r1 = sA + (row_base + g + 8) * XSTRIDE + 8 * s + tg;
    a[0] = r0[0]; a[1] = r1[0]; a[2] = r0[4]; a[3] = r1[4];
}
// Load B frag (2 words) for warp channel-tile nt, k-step s.
__device__ __forceinline__ void load_b(const unsigned* __restrict__ sB, int nt,
                                       int g, int tg, int s, unsigned (&b)[2]) {
    const unsigned* r = sB + (8 * nt + g) * XSTRIDE + 8 * s + tg;
    b[0] = r[0]; b[1] = r[4];
}

// ----------------------------------------------------------------------------
// Per-degree mma stages (compile-time L keeps accumulator indices literal)
// ----------------------------------------------------------------------------
template<int L>
__device__ __forceinline__ void stageA_mma(const unsigned* __restrict__ sm,
                                           int nt, int g, int tg,
                                           float (&yL)[M_DIM][4], float (&yR)[M_DIM][4]) {
    constexpr int base = L * L;
    constexpr int msz  = 2 * L + 1;
    const unsigned* xh = sm + OFF_XH;
    const unsigned* xl = sm + OFF_XL;
    const unsigned* wlh = sm + OFF_WLH;
    const unsigned* wll = sm + OFF_WLL;
    const unsigned* wrh = sm + OFF_WRH;
    const unsigned* wrl = sm + OFF_WRL;
    #pragma unroll
    for (int s = 0; s < 8; ++s) {
        unsigned bLh[2], bLl[2], bRh[2], bRl[2];
        load_b(wlh, nt, g, tg, s, bLh);
        load_b(wll, nt, g, tg, s, bLl);
        load_b(wrh, nt, g, tg, s, bRh);
        load_b(wrl, nt, g, tg, s, bRl);
        #pragma unroll
        for (int ml = 0; ml < msz; ++ml) {
            unsigned ah[4], al[4];
            load_a(xh, (base + ml) * 16, g, tg, s, ah);
            load_a(xl, (base + ml) * 16, g, tg, s, al);
            mma16(yL[base + ml], ah, bLh);
            mma16(yL[base + ml], ah, bLl);
            mma16(yL[base + ml], al, bLh);
            mma16(yR[base + ml], ah, bRh);
            mma16(yR[base + ml], ah, bRl);
            mma16(yR[base + ml], al, bRh);
        }
    }
}

template<int L>
__device__ __forceinline__ void stageC_mma(const unsigned* __restrict__ sm,
                                           int nt, int g, int tg,
                                           float (&fo)[M_DIM][4]) {
    constexpr int base = L * L;
    constexpr int msz  = 2 * L + 1;
    const unsigned* th  = sm + OFF_XH;
    const unsigned* tl  = sm + OFF_XL;
    const unsigned* wfh = sm + OFF_WLH;
    const unsigned* wfl = sm + OFF_WLL;
    #pragma unroll
    for (int s = 0; s < 8; ++s) {
        unsigned bh[2], bl[2];
        load_b(wfh, nt, g, tg, s, bh);
        load_b(wfl, nt, g, tg, s, bl);
        #pragma unroll
        for (int ml = 0; ml < msz; ++ml) {
            unsigned ah[4], al[4];
            load_a(th, (base + ml) * 16, g, tg, s, ah);
            load_a(tl, (base + ml) * 16, g, tg, s, al);
            mma16(fo[base + ml], ah, bh);
            mma16(fo[base + ml], ah, bl);
            mma16(fo[base + ml], al, bh);
        }
    }
}

// CG tensor product for one (node, channel)
__device__ __forceinline__ void tp_compute(const float (&L)[M_DIM], const float (&R)[M_DIM],
                                           float (&t)[M_DIM], const W3J& P) {
    {   // (2,2,0)
        float v = 0.f;
        #pragma unroll
        for (int i = 0; i < 5; ++i)
            #pragma unroll
            for (int j = 0; j < 5; ++j)
                v = fmaf(P.w220[i * 5 + j], L[4 + i] * R[4 + j], v);
        t[0] = v;
    }
    #pragma unroll
    for (int k = 0; k < 3; ++k) {   // (1,2,1)
        float v = 0.f;
        #pragma unroll
        for (int i = 0; i < 3; ++i)
            #pragma unroll
            for (int j = 0; j < 5; ++j)
                v = fmaf(P.w121[(i * 5 + j) * 3 + k], L[1 + i] * R[4 + j], v);
        t[1 + k] = v;
    }
    #pragma unroll
    for (int k = 0; k < 5; ++k) {   // (1,1,2)
        float v = 0.f;
        #pragma unroll
        for (int i = 0; i < 3; ++i)
            #pragma unroll
            for (int j = 0; j < 3; ++j)
                v = fmaf(P.w112[(i * 3 + j) * 5 + k], L[1 + i] * R[1 + j], v);
        t[4 + k] = v;
    }
}

// ----------------------------------------------------------------------------
// Fused kernel. 512 threads = 16 warps; warp nt owns channels [8nt, 8nt+8).
// GEMM rows ordered (m*16 + node). All operands pre-split to bf16 hi/lo in smem;
// inner loops are pure LDS + HMMA (bf16x3 ~ fp32 precision).
// ----------------------------------------------------------------------------
__global__ __launch_bounds__(THREADS, 1)
void b2i_bf16x3_kernel(const float* __restrict__ x,
                       const float* __restrict__ Wl, const float* __restrict__ bl,
                       const float* __restrict__ Wr, const float* __restrict__ br,
                       const float* __restrict__ Wf, const float* __restrict__ bf,
                       float* __restrict__ out, const W3J P)
{
    extern __shared__ unsigned sm[];

    const int tid  = threadIdx.x;
    const int lane = tid & 31;
    const int nt   = tid >> 5;
    const int g    = lane >> 2;
    const int tg   = lane & 3;
    const size_t node0 = (size_t)blockIdx.x * B_NODES;

    // ---- stage + split x tile: [node][m][c] -> rows (m*16+node), hi/lo words ----
    {
        #pragma unroll
        for (int i = 0; i < 9; ++i) {
            const int idx = tid + i * THREADS;     // 0..4607 float4s
            const int row = idx >> 5;              // node*9+m
            const int c4  = idx & 31;
            const int node = (row * 57) >> 9;      // row/9 for row<144
            const int m    = row - node * 9;
            const float4 v = __ldg(reinterpret_cast<const float4*>(
                x + ((node0 + node) * M_DIM + m) * C_DIM + c4 * 4));
            unsigned h0, l0, h1, l1;
            split_pair(v.x, v.y, h0, l0);
            split_pair(v.z, v.w, h1, l1);
            const int w = (m * 16 + node) * XSTRIDE + c4 * 2;
            sm[OFF_XH + w] = h0; sm[OFF_XH + w + 1] = h1;
            sm[OFF_XL + w] = l0; sm[OFF_XL + w + 1] = l1;
        }
    }

    // =========================================================================
    // Stage A: y_l / y_r via bf16x3 mma
    // =========================================================================
    float yL[M_DIM][4], yR[M_DIM][4];
    #pragma unroll
    for (int m = 0; m < M_DIM; ++m)
        #pragma unroll
        for (int c = 0; c < 4; ++c) { yL[m][c] = 0.f; yR[m][c] = 0.f; }

    #pragma unroll
    for (int l = 0; l < 3; ++l) {
        __syncthreads();   // x ready (l=0) / prev-l mma done reading weights
        {   // stage + split Wl_l, Wr_l
            #pragma unroll
            for (int i = 0; i < 8; ++i) {
                const int idx = tid + i * THREADS;   // 0..4095
                const int row = idx >> 5;
                const int c4  = idx & 31;
                const float4 a = __ldg(reinterpret_cast<const float4*>(
                    Wl + (size_t)(l * 128 + row) * 128 + c4 * 4));
                const float4 b = __ldg(reinterpret_cast<const float4*>(
                    Wr + (size_t)(l * 128 + row) * 128 + c4 * 4));
                unsigned h0, l0, h1, l1;
                const int w = row * XSTRIDE + c4 * 2;
                split_pair(a.x, a.y, h0, l0);
                split_pair(a.z, a.w, h1, l1);
                sm[OFF_WLH + w] = h0; sm[OFF_WLH + w + 1] = h1;
                sm[OFF_WLL + w] = l0; sm[OFF_WLL + w + 1] = l1;
                split_pair(b.x, b.y, h0, l0);
                split_pair(b.z, b.w, h1, l1);
                sm[OFF_WRH + w] = h0; sm[OFF_WRH + w + 1] = h1;
                sm[OFF_WRL + w] = l0; sm[OFF_WRL + w + 1] = l1;
            }
        }
        __syncthreads();
        if (l == 0)      stageA_mma<0>(sm, nt, g, tg, yL, yR);
        else if (l == 1) stageA_mma<1>(sm, nt, g, tg, yL, yR);
        else             stageA_mma<2>(sm, nt, g, tg, yL, yR);
    }

    __syncthreads();   // all mma reads of x complete before t overwrites it

    // =========================================================================
    // Stage B: thread-local tensor product on fragments; t split -> x region
    // Thread owns (node g, ch0),(node g, ch0+1),(node g+8, ch0),(node g+8, ch0+1)
    // where ch0 = 8nt + 2tg. Adjacent channels pack into one bf16x2 word.
    // =========================================================================
    {
        const int ch0 = 8 * nt + 2 * tg;
        const int cw  = ch0 >> 1;              // word column
        const float bl0 = bl[ch0], bl1 = bl[ch0 + 1];
        const float br0 = br[ch0], br1 = br[ch0 + 1];

        float La[M_DIM], Ra[M_DIM], Lb[M_DIM], Rb[M_DIM], ta[M_DIM], tb[M_DIM];

        // node g
        #pragma unroll
        for (int m = 0; m < M_DIM; ++m) {
            La[m] = yL[m][0]; Ra[m] = yR[m][0];
            Lb[m] = yL[m][1]; Rb[m] = yR[m][1];
        }
        La[0] += bl0; Ra[0] += br0; Lb[0] += bl1; Rb[0] += br1;
        tp_compute(La, Ra, ta, P);
        tp_compute(Lb, Rb, tb, P);
        #pragma unroll
        for (int m = 0; m < M_DIM; ++m) {
            unsigned h, lo;
            split_pair(ta[m], tb[m], h, lo);
            const int w = (m * 16 + g) * XSTRIDE + cw;
            sm[OFF_XH + w] = h; sm[OFF_XL + w] = lo;
        }

        // node g+8
        #pragma unroll
        for (int m = 0; m < M_DIM; ++m) {
            La[m] = yL[m][2]; Ra[m] = yR[m][2];
            Lb[m] = yL[m][3]; Rb[m] = yR[m][3];
        }
        La[0] += bl0; Ra[0] += br0; Lb[0] += bl1; Rb[0] += br1;
        tp_compute(La, Ra, ta, P);
        tp_compute(Lb, Rb, tb, P);
        #pragma unroll
        for (int m = 0; m < M_DIM; ++m) {
            unsigned h, lo;
            split_pair(ta[m], tb[m], h, lo);
            const int w = (m * 16 + g + 8) * XSTRIDE + cw;
            sm[OFF_XH + w] = h; sm[OFF_XL + w] = lo;
        }
    }

    // =========================================================================
    // Stage C: final linear via bf16x3 mma
    // =========================================================================
    float fo[M_DIM][4];
    #pragma unroll
    for (int m = 0; m < M_DIM; ++m)
        #pragma unroll
        for (int c = 0; c < 4; ++c) fo[m][c] = 0.f;

    #pragma unroll
    for (int l = 0; l < 3; ++l) {
        __syncthreads();   // t stores done (l=0) / prev-l mma done reading weights
        {   // stage + split Wf_l
            #pragma unroll
            for (int i = 0; i < 8; ++i) {
                const int idx = tid + i * THREADS;
                const int row = idx >> 5;
                const int c4  = idx & 31;
                const float4 a = __ldg(reinterpret_cast<const float4*>(
                    Wf + (size_t)(l * 128 + row) * 128 + c4 * 4));
                unsigned h0, l0, h1, l1;
                split_pair(a.x, a.y, h0, l0);
                split_pair(a.z, a.w, h1, l1);
                const int w = row * XSTRIDE + c4 * 2;
                sm[OFF_WLH + w] = h0; sm[OFF_WLH + w + 1] = h1;
                sm[OFF_WLL + w] = l0; sm[OFF_WLL + w + 1] = l1;
            }
        }
        __syncthreads();
        if (l == 0)      stageC_mma<0>(sm, nt, g, tg, fo);
        else if (l == 1) stageC_mma<1>(sm, nt, g, tg, fo);
        else             stageC_mma<2>(sm, nt, g, tg, fo);
    }

    // ---- bias + write out ----
    {
        const int ch0 = 8 * nt + 2 * tg;
        const float bf0 = bf[ch0], bf1 = bf[ch0 + 1];
        #pragma unroll
        for (int m = 0; m < M_DIM; ++m) {
            float v0 = fo[m][0], v1 = fo[m][1], v2 = fo[m][2], v3 = fo[m][3];
            if (m == 0) { v0 += bf0; v1 += bf1; v2 += bf0; v3 += bf1; }
            const size_t nA = node0 + g;
            const size_t nB = node0 + g + 8;
            *reinterpret_cast<float2*>(out + (nA * M_DIM + m) * C_DIM + ch0) =
                make_float2(v0, v1);
            *reinterpret_cast<float2*>(out + (nB * M_DIM + m) * C_DIM + ch0) =
                make_float2(v2, v3);
        }
    }
}

// ----------------------------------------------------------------------------
// Launch
// ----------------------------------------------------------------------------
extern "C" void kernel_launch(void* const* d_in, const int* in_sizes, int n_in,
                              void* d_out, int out_size)
{
    const float* x  = (const float*)d_in[0];
    const float* Wl = (const float*)d_in[1];
    const float* bl = (const float*)d_in[2];
    const float* Wr = (const float*)d_in[3];
    const float* br = (const float*)d_in[4];
    const float* Wf = (const float*)d_in[5];
    const float* bf = (const float*)d_in[6];
    float* out = (float*)d_out;

    W3J P;
    hw3j::build(P);

    cudaFuncSetAttribute(b2i_bf16x3_kernel, cudaFuncAttributeMaxDynamicSharedMemorySize, SMEM_BYTES);

    b2i_bf16x3_kernel<<<NNODES / B_NODES, THREADS, SMEM_BYTES>>>(
        x, Wl, bl, Wr, br, Wf, bf, out, P);
}

// round 8
// speedup vs baseline: 17.7934x; 1.1432x over previous
#include <cuda_runtime.h>
#include <cmath>
#include <complex>
#include <algorithm>

// ----------------------------------------------------------------------------
// Problem constants
// ----------------------------------------------------------------------------
#define NNODES   50000
#define C_DIM    128
#define M_DIM    9
#define B_NODES  16
#define THREADS  256

// Word (b32 = bf16x2) layouts
#define XSTRIDE  68                        // row stride in words (==4 mod 32), 272 B
#define SXW      (144 * XSTRIDE)           // 9792 words per x part (hi or lo)
#define SWW      (128 * XSTRIDE)           // 8704 words per weight part

// smem word offsets
#define OFF_XH   0
#define OFF_XL   (SXW)
#define OFF_WLH  (2 * SXW)
#define OFF_WLL  (2 * SXW + SWW)
#define OFF_WRH  (2 * SXW + 2 * SWW)
#define OFF_WRL  (2 * SXW + 3 * SWW)
#define SMEM_WORDS (2 * SXW + 4 * SWW)     // 54400 words
#define SMEM_BYTES (SMEM_WORDS * 4)        // 217600 B

// Wigner-3j tables (alpha folded in), kernel arg.
struct W3J {
    float w220[25];
    float w121[45];
    float w112[45];
};

// ----------------------------------------------------------------------------
// Host-side Wigner 3j (literal translation of the reference, double precision)
// ----------------------------------------------------------------------------
namespace hw3j {
typedef std::complex<double> cd;

static inline double fact(int n) { double r = 1.0; for (int i = 2; i <= n; ++i) r *= (double)i; return r; }

static double su2_cg(int j1, int m1, int j2, int m2, int j3, int m3) {
    if (m1 + m2 != m3) return 0.0;
    int vmin = std::max(std::max(-j1 + j2 + m3, -j1 + m1), 0);
    int vmax = std::min(std::min(j2 + j3 + m1, j3 - j1 + j2), j3 + m3);
    double pref = std::sqrt((2.0 * j3 + 1.0)
        * fact(j3 + j1 - j2) * fact(j3 - j1 + j2) * fact(j1 + j2 - j3) / fact(j1 + j2 + j3 + 1)
        * fact(j3 + m3) * fact(j3 - m3)
        / (fact(j1 - m1) * fact(j1 + m1) * fact(j2 - m2) * fact(j2 + m2)));
    double s = 0.0;
    for (int v = vmin; v <= vmax; ++v) {
        double sgn = ((v + j2 + m2) & 1) ? -1.0 : 1.0;
        s += sgn / fact(v) * fact(j2 + j3 + m1 - v) * fact(j1 - m1 + v)
             / (fact(j3 - j1 + j2 - v) * fact(j3 + m3 - v) * fact(v + j1 - j2 - m3));
    }
    return pref * s;
}

static void qmat(int l, cd q[5][5]) {
    for (int a = 0; a < 5; ++a) for (int b = 0; b < 5; ++b) q[a][b] = cd(0, 0);
    const double is2 = 1.0 / std::sqrt(2.0);
    for (int m = -l; m < 0; ++m) {
        q[l + m][l - m] = cd(is2, 0.0);
        q[l + m][l + m] = cd(0.0, -is2);
    }
    q[l][l] = cd(1.0, 0.0);
    for (int m = 1; m <= l; ++m) {
        double sg = (m & 1) ? -1.0 : 1.0;
        q[l + m][l + m] = cd(sg * is2, 0.0);
        q[l + m][l - m] = cd(0.0, sg * is2);
    }
    cd ph;
    switch (l & 3) {
        case 0: ph = cd( 1,  0); break;
        case 1: ph = cd( 0, -1); break;
        case 2: ph = cd(-1,  0); break;
        default: ph = cd(0,  1); break;
    }
    for (int a = 0; a < 2 * l + 1; ++a) for (int b = 0; b < 2 * l + 1; ++b) q[a][b] *= ph;
}

static void wig3j(int l1, int l2, int l3, float* out) {
    const int d1 = 2 * l1 + 1, d2 = 2 * l2 + 1, d3 = 2 * l3 + 1;
    cd Q1[5][5], Q2[5][5], Q3[5][5];
    qmat(l1, Q1); qmat(l2, Q2); qmat(l3, Q3);
    static cd Csu2[5][5][5];
    for (int i = 0; i < d1; ++i)
        for (int k = 0; k < d2; ++k)
            for (int n = 0; n < d3; ++n)
                Csu2[i][k][n] = cd(su2_cg(l1, i - l1, l2, k - l2, l3, n - l3), 0.0);
    static double Cr[5][5][5];
    double nrm = 0.0;
    for (int j = 0; j < d1; ++j)
        for (int ll = 0; ll < d2; ++ll)
            for (int m = 0; m < d3; ++m) {
                cd acc(0, 0);
                for (int i = 0; i < d1; ++i)
                    for (int k = 0; k < d2; ++k)
                        for (int n = 0; n < d3; ++n)
                            acc += Q1[i][j] * Q2[k][ll] * std::conj(Q3[n][m]) * Csu2[i][k][n];
                Cr[j][ll][m] = acc.real();
                nrm += acc.real() * acc.real();
            }
    nrm = std::sqrt(nrm);
    int idx = 0;
    for (int j = 0; j < d1; ++j)
        for (int ll = 0; ll < d2; ++ll)
            for (int m = 0; m < d3; ++m)
                out[idx++] = (float)(Cr[j][ll][m] / nrm);
}

static void build(W3J& P) {
    float c220[25], c121[45], c112[45];
    wig3j(2, 2, 0, c220);
    wig3j(1, 2, 1, c121);
    wig3j(1, 1, 2, c112);
    const float a121 = std::sqrt(3.0f), a112 = std::sqrt(5.0f);
    for (int i = 0; i < 25; ++i) P.w220[i] = c220[i];
    for (int i = 0; i < 45; ++i) P.w121[i] = a121 * c121[i];
    for (int i = 0; i < 45; ++i) P.w112[i] = a112 * c112[i];
}
} // namespace hw3j

// ----------------------------------------------------------------------------
// bf16 split + mma + ldmatrix helpers
// ----------------------------------------------------------------------------
__device__ __forceinline__ unsigned pack_bf16(float e0, float e1) {
    unsigned r;
    asm("cvt.rn.bf16x2.f32 %0, %1, %2;" : "=r"(r) : "f"(e1), "f"(e0));
    return r;
}
__device__ __forceinline__ void split_pair(float e0, float e1, unsigned& hi, unsigned& lo) {
    hi = pack_bf16(e0, e1);
    const float h0 = __uint_as_float(hi << 16);
    const float h1 = __uint_as_float(hi & 0xffff0000u);
    lo = pack_bf16(e0 - h0, e1 - h1);
}
__device__ __forceinline__ void mma16(float* d, const unsigned (&a)[4], const unsigned (&b)[2]) {
    asm("mma.sync.aligned.m16n8k16.row.col.f32.bf16.bf16.f32 "
        "{%0,%1,%2,%3}, {%4,%5,%6,%7}, {%8,%9}, {%0,%1,%2,%3};"
        : "+f"(d[0]), "+f"(d[1]), "+f"(d[2]), "+f"(d[3])
        : "r"(a[0]), "r"(a[1]), "r"(a[2]), "r"(a[3]), "r"(b[0]), "r"(b[1]));
}
__device__ __forceinline__ void ldsm_x4(unsigned (&a)[4], unsigned addr) {
    asm volatile("ldmatrix.sync.aligned.m8n8.x4.shared.b16 {%0,%1,%2,%3}, [%4];"
                 : "=r"(a[0]), "=r"(a[1]), "=r"(a[2]), "=r"(a[3]) : "r"(addr));
}
__device__ __forceinline__ void ldsm_x2(unsigned (&b)[2], unsigned addr) {
    asm volatile("ldmatrix.sync.aligned.m8n8.x2.shared.b16 {%0,%1}, [%2];"
                 : "=r"(b[0]), "=r"(b[1]) : "r"(addr));
}

// ----------------------------------------------------------------------------
// Per-degree mma stages. Warp covers n=16 (two 8-wide B tiles). All addresses
// are byte offsets into shared memory (ldmatrix lane-address pattern).
//   aab: A lane base (this thread's ldmatrix address component)
//   bab: B lane base
// A addr(part, mtile, s) = part*4 + mtile*16*272 + s*32 + aab
// B addr(part, j, s)     = part*4 + (16*wq+8*j)*272 + s*32 + bab
// ----------------------------------------------------------------------------
template<int L>
__device__ __forceinline__ void stageA_mma(unsigned aab, unsigned bab,
                                           float (&yL)[M_DIM][2][4], float (&yR)[M_DIM][2][4]) {
    constexpr int base = L * L;
    constexpr int msz  = 2 * L + 1;
    #pragma unroll
    for (int s = 0; s < 8; ++s) {
        unsigned bLh[2][2], bLl[2][2], bRh[2][2], bRl[2][2];
        #pragma unroll
        for (int j = 0; j < 2; ++j) {
            const unsigned bo = bab + j * (8 * 272) + s * 32;
            ldsm_x2(bLh[j], bo + OFF_WLH * 4);
            ldsm_x2(bLl[j], bo + OFF_WLL * 4);
            ldsm_x2(bRh[j], bo + OFF_WRH * 4);
            ldsm_x2(bRl[j], bo + OFF_WRL * 4);
        }
        #pragma unroll
        for (int ml = 0; ml < msz; ++ml) {
            unsigned ah[4], al[4];
            const unsigned ao = aab + (base + ml) * (16 * 272) + s * 32;
            ldsm_x4(ah, ao + OFF_XH * 4);
            ldsm_x4(al, ao + OFF_XL * 4);
            #pragma unroll
            for (int j = 0; j < 2; ++j) {
                mma16(yL[base + ml][j], ah, bLh[j]);
                mma16(yL[base + ml][j], ah, bLl[j]);
                mma16(yL[base + ml][j], al, bLh[j]);
                mma16(yR[base + ml][j], ah, bRh[j]);
                mma16(yR[base + ml][j], ah, bRl[j]);
                mma16(yR[base + ml][j], al, bRh[j]);
            }
        }
    }
}

template<int L>
__device__ __forceinline__ void stageC_mma(unsigned aab, unsigned bab,
                                           float (&fo)[M_DIM][2][4]) {
    constexpr int base = L * L;
    constexpr int msz  = 2 * L + 1;
    #pragma unroll
    for (int s = 0; s < 8; ++s) {
        unsigned bh[2][2], bl[2][2];
        #pragma unroll
        for (int j = 0; j < 2; ++j) {
            const unsigned bo = bab + j * (8 * 272) + s * 32;
            ldsm_x2(bh[j], bo + OFF_WLH * 4);
            ldsm_x2(bl[j], bo + OFF_WLL * 4);
        }
        #pragma unroll
        for (int ml = 0; ml < msz; ++ml) {
            unsigned ah[4], al[4];
            const unsigned ao = aab + (base + ml) * (16 * 272) + s * 32;
            ldsm_x4(ah, ao + OFF_XH * 4);
            ldsm_x4(al, ao + OFF_XL * 4);
            #pragma unroll
            for (int j = 0; j < 2; ++j) {
                mma16(fo[base + ml][j], ah, bh[j]);
                mma16(fo[base + ml][j], ah, bl[j]);
                mma16(fo[base + ml][j], al, bh[j]);
            }
        }
    }
}

// CG tensor product for one (node, channel)
__device__ __forceinline__ void tp_compute(const float (&L)[M_DIM], const float (&R)[M_DIM],
                                           float (&t)[M_DIM], const W3J& P) {
    {   // (2,2,0)
        float v = 0.f;
        #pragma unroll
        for (int i = 0; i < 5; ++i)
            #pragma unroll
            for (int j = 0; j < 5; ++j)
                v = fmaf(P.w220[i * 5 + j], L[4 + i] * R[4 + j], v);
        t[0] = v;
    }
    #pragma unroll
    for (int k = 0; k < 3; ++k) {   // (1,2,1)
        float v = 0.f;
        #pragma unroll
        for (int i = 0; i < 3; ++i)
            #pragma unroll
            for (int j = 0; j < 5; ++j)
                v = fmaf(P.w121[(i * 5 + j) * 3 + k], L[1 + i] * R[4 + j], v);
        t[1 + k] = v;
    }
    #pragma unroll
    for (int k = 0; k < 5; ++k) {   // (1,1,2)
        float v = 0.f;
        #pragma unroll
        for (int i = 0; i < 3; ++i)
            #pragma unroll
            for (int j = 0; j < 3; ++j)
                v = fmaf(P.w112[(i * 3 + j) * 5 + k], L[1 + i] * R[1 + j], v);
        t[4 + k] = v;
    }
}

// ----------------------------------------------------------------------------
// Fused kernel. 256 threads = 8 warps; warp wq owns channels [16wq, 16wq+16).
// GEMM rows ordered (m*16 + node); operands pre-split to bf16 hi/lo in smem;
// fragment loads via ldmatrix.
// ----------------------------------------------------------------------------
__global__ __launch_bounds__(THREADS, 1)
void b2i_bf16x3_kernel(const float* __restrict__ x,
                       const float* __restrict__ Wl, const float* __restrict__ bl,
                       const float* __restrict__ Wr, const float* __restrict__ br,
                       const float* __restrict__ Wf, const float* __restrict__ bf,
                       float* __restrict__ out, const W3J P)
{
    extern __shared__ unsigned sm[];

    const int tid  = threadIdx.x;
    const int lane = tid & 31;
    const int wq   = tid >> 5;            // warp id: channel 16-block
    const int g    = lane >> 2;
    const int tg   = lane & 3;
    const size_t node0 = (size_t)blockIdx.x * B_NODES;

    const unsigned smb = (unsigned)__cvta_generic_to_shared(sm);
    // ldmatrix lane-address components (bytes)
    const unsigned aab = smb + (((lane & 7) + ((lane >> 3) & 1) * 8) * XSTRIDE
                                + (lane >> 4) * 4) * 4;
    const unsigned bab = smb + ((lane & 7) * XSTRIDE + ((lane >> 3) & 1) * 4) * 4
                             + (16 * wq) * 272;

    // ---- stage + split x tile: [node][m][c] -> rows (m*16+node), hi/lo words ----
    {
        #pragma unroll
        for (int i = 0; i < 18; ++i) {
            const int idx = tid + i * THREADS;     // 0..4607 float4s
            const int row = idx >> 5;              // node*9+m
            const int c4  = idx & 31;
            const int node = (row * 57) >> 9;      // row/9 for row<144
            const int m    = row - node * 9;
            const float4 v = __ldg(reinterpret_cast<const float4*>(
                x + ((node0 + node) * M_DIM + m) * C_DIM + c4 * 4));
            unsigned h0, l0, h1, l1;
            split_pair(v.x, v.y, h0, l0);
            split_pair(v.z, v.w, h1, l1);
            const int w = (m * 16 + node) * XSTRIDE + c4 * 2;
            *reinterpret_cast<uint2*>(sm + OFF_XH + w) = make_uint2(h0, h1);
            *reinterpret_cast<uint2*>(sm + OFF_XL + w) = make_uint2(l0, l1);
        }
    }

    // =========================================================================
    // Stage A: y_l / y_r via bf16x3 mma (n=16 per warp)
    // =========================================================================
    float yL[M_DIM][2][4], yR[M_DIM][2][4];
    #pragma unroll
    for (int m = 0; m < M_DIM; ++m)
        #pragma unroll
        for (int j = 0; j < 2; ++j)
            #pragma unroll
            for (int c = 0; c < 4; ++c) { yL[m][j][c] = 0.f; yR[m][j][c] = 0.f; }

    #pragma unroll
    for (int l = 0; l < 3; ++l) {
        __syncthreads();   // x ready (l=0) / prev-l mma done reading weights
        {   // stage + split Wl_l, Wr_l
            #pragma unroll
            for (int i = 0; i < 16; ++i) {
                const int idx = tid + i * THREADS;   // 0..4095
                const int row = idx >> 5;
                const int c4  = idx & 31;
                const float4 a = __ldg(reinterpret_cast<const float4*>(
                    Wl + (size_t)(l * 128 + row) * 128 + c4 * 4));
                const float4 b = __ldg(reinterpret_cast<const float4*>(
                    Wr + (size_t)(l * 128 + row) * 128 + c4 * 4));
                unsigned h0, l0, h1, l1;
                const int w = row * XSTRIDE + c4 * 2;
                split_pair(a.x, a.y, h0, l0);
                split_pair(a.z, a.w, h1, l1);
                *reinterpret_cast<uint2*>(sm + OFF_WLH + w) = make_uint2(h0, h1);
                *reinterpret_cast<uint2*>(sm + OFF_WLL + w) = make_uint2(l0, l1);
                split_pair(b.x, b.y, h0, l0);
                split_pair(b.z, b.w, h1, l1);
                *reinterpret_cast<uint2*>(sm + OFF_WRH + w) = make_uint2(h0, h1);
                *reinterpret_cast<uint2*>(sm + OFF_WRL + w) = make_uint2(l0, l1);
            }
        }
        __syncthreads();
        if (l == 0)      stageA_mma<0>(aab, bab, yL, yR);
        else if (l == 1) stageA_mma<1>(aab, bab, yL, yR);
        else             stageA_mma<2>(aab, bab, yL, yR);
    }

    __syncthreads();   // all mma reads of x complete before t overwrites it

    // =========================================================================
    // Stage B: thread-local tensor product; t split -> x region.
    // Per tile j: channels ch0=16wq+8j+2tg, ch0+1; nodes g, g+8.
    // Frag cols: [j][0]=(g,ch0) [j][1]=(g,ch0+1) [j][2]=(g+8,ch0) [j][3]=(g+8,ch0+1)
    // =========================================================================
    #pragma unroll
    for (int j = 0; j < 2; ++j) {
        const int ch0 = 16 * wq + 8 * j + 2 * tg;
        const int cw  = ch0 >> 1;
        const float bl0 = bl[ch0], bl1 = bl[ch0 + 1];
        const float br0 = br[ch0], br1 = br[ch0 + 1];

        float La[M_DIM], Ra[M_DIM], Lb[M_DIM], Rb[M_DIM], ta[M_DIM], tb[M_DIM];

        // node g
        #pragma unroll
        for (int m = 0; m < M_DIM; ++m) {
            La[m] = yL[m][j][0]; Ra[m] = yR[m][j][0];
            Lb[m] = yL[m][j][1]; Rb[m] = yR[m][j][1];
        }
        La[0] += bl0; Ra[0] += br0; Lb[0] += bl1; Rb[0] += br1;
        tp_compute(La, Ra, ta, P);
        tp_compute(Lb, Rb, tb, P);
        #pragma unroll
        for (int m = 0; m < M_DIM; ++m) {
            unsigned h, lo;
            split_pair(ta[m], tb[m], h, lo);
            const int w = (m * 16 + g) * XSTRIDE + cw;
            sm[OFF_XH + w] = h; sm[OFF_XL + w] = lo;
        }

        // node g+8
        #pragma unroll
        for (int m = 0; m < M_DIM; ++m) {
            La[m] = yL[m][j][2]; Ra[m] = yR[m][j][2];
            Lb[m] = yL[m][j][3]; Rb[m] = yR[m][j][3];
        }
        La[0] += bl0; Ra[0] += br0; Lb[0] += bl1; Rb[0] += br1;
        tp_compute(La, Ra, ta, P);
        tp_compute(Lb, Rb, tb, P);
        #pragma unroll
        for (int m = 0; m < M_DIM; ++m) {
            unsigned h, lo;
            split_pair(ta[m], tb[m], h, lo);
            const int w = (m * 16 + g + 8) * XSTRIDE + cw;
            sm[OFF_XH + w] = h; sm[OFF_XL + w] = lo;
        }
    }

    // =========================================================================
    // Stage C: final linear via bf16x3 mma
    // =========================================================================
    float fo[M_DIM][2][4];
    #pragma unroll
    for (int m = 0; m < M_DIM; ++m)
        #pragma unroll
        for (int j = 0; j < 2; ++j)
            #pragma unroll
            for (int c = 0; c < 4; ++c) fo[m][j][c] = 0.f;

    #pragma unroll
    for (int l = 0; l < 3; ++l) {
        __syncthreads();   // t stores done (l=0) / prev-l mma done reading weights
        {   // stage + split Wf_l
            #pragma unroll
            for (int i = 0; i < 16; ++i) {
                const int idx = tid + i * THREADS;
                const int row = idx >> 5;
                const int c4  = idx & 31;
                const float4 a = __ldg(reinterpret_cast<const float4*>(
                    Wf + (size_t)(l * 128 + row) * 128 + c4 * 4));
                unsigned h0, l0, h1, l1;
                split_pair(a.x, a.y, h0, l0);
                split_pair(a.z, a.w, h1, l1);
                const int w = row * XSTRIDE + c4 * 2;
                *reinterpret_cast<uint2*>(sm + OFF_WLH + w) = make_uint2(h0, h1);
                *reinterpret_cast<uint2*>(sm + OFF_WLL + w) = make_uint2(l0, l1);
            }
        }
        __syncthreads();
        if (l == 0)      stageC_mma<0>(aab, bab, fo);
        else if (l == 1) stageC_mma<1>(aab, bab, fo);
        else             stageC_mma<2>(aab, bab, fo);
    }

    // ---- bias + write out ----
    #pragma unroll
    for (int j = 0; j < 2; ++j) {
        const int ch0 = 16 * wq + 8 * j + 2 * tg;
        const float bf0 = bf[ch0], bf1 = bf[ch0 + 1];
        #pragma unroll
        for (int m = 0; m < M_DIM; ++m) {
            float v0 = fo[m][j][0], v1 = fo[m][j][1], v2 = fo[m][j][2], v3 = fo[m][j][3];
            if (m == 0) { v0 += bf0; v1 += bf1; v2 += bf0; v3 += bf1; }
            const size_t nA = node0 + g;
            const size_t nB = node0 + g + 8;
            *reinterpret_cast<float2*>(out + (nA * M_DIM + m) * C_DIM + ch0) =
                make_float2(v0, v1);
            *reinterpret_cast<float2*>(out + (nB * M_DIM + m) * C_DIM + ch0) =
                make_float2(v2, v3);
        }
    }
}

// ----------------------------------------------------------------------------
// Launch
// ----------------------------------------------------------------------------
extern "C" void kernel_launch(void* const* d_in, const int* in_sizes, int n_in,
                              void* d_out, int out_size)
{
    const float* x  = (const float*)d_in[0];
    const float* Wl = (const float*)d_in[1];
    const float* bl = (const float*)d_in[2];
    const float* Wr = (const float*)d_in[3];
    const float* br = (const float*)d_in[4];
    const float* Wf = (const float*)d_in[5];
    const float* bf = (const float*)d_in[6];
    float* out = (float*)d_out;

    W3J P;
    hw3j::build(P);

    cudaFuncSetAttribute(b2i_bf16x3_kernel, cudaFuncAttributeMaxDynamicSharedMemorySize, SMEM_BYTES);

    b2i_bf16x3_kernel<<<NNODES / B_NODES, THREADS, SMEM_BYTES>>>(
        x, Wl, bl, Wr, br, Wf, bf, out, P);
}